// round 2
// baseline (speedup 1.0000x reference)
#include <cuda_runtime.h>
#include <cuda_bf16.h>

// PepEmbedding: out[b,h,:] = soft_threshold(emb[x[b,h],:], s[x[b,h],:])
//   soft_threshold(v,s) = sign(v)*relu(|v| - sigmoid(s))
//
// Shapes: x[16384,50] i32, emb[1e6,128] f32, s[1e6,128] f32, out[819200,128] f32.
//
// Strategy (R2): the workload is HBM-bound; 260K of the 819K gathers are
// duplicate indices that mostly miss L2 because they're temporally scattered.
// Bucket rows by index range (1024 buckets, ~1 MB emb + 1 MB s per bucket) and
// process bucket-major, so every unique table row is read from DRAM exactly
// once and duplicates hit L2. Output writes use streaming (evict-first) stores
// to avoid evicting the bucket-resident rows.

#define ROWS        (16384 * 50)   // 819,200
#define NBUCKETS    1024
#define BUCKET_SHIFT 10            // idx >> 10  -> bucket 0..976
#define VEC_PER_ROW 32             // 128 floats / float4

// Scratch (device globals — no allocation allowed in kernel_launch)
__device__ int                bucket_count[NBUCKETS];
__device__ int                bucket_cursor[NBUCKETS];
__device__ unsigned long long sorted_key[ROWS];   // (idx << 32) | row

// ---------------------------------------------------------------- init
__global__ void k_init() {
    int t = threadIdx.x;
    bucket_count[t] = 0;
}

// ---------------------------------------------------------------- histogram
__global__ __launch_bounds__(1024)
void k_hist(const int* __restrict__ x) {
    __shared__ int hist[NBUCKETS];
    hist[threadIdx.x] = 0;
    __syncthreads();

    int row = blockIdx.x * 1024 + threadIdx.x;   // grid covers ROWS exactly
    int b = x[row] >> BUCKET_SHIFT;
    atomicAdd(&hist[b], 1);
    __syncthreads();

    if (hist[threadIdx.x]) atomicAdd(&bucket_count[threadIdx.x], hist[threadIdx.x]);
}

// ---------------------------------------------------------------- scan (1 block)
__global__ __launch_bounds__(1024)
void k_scan() {
    __shared__ int tmp[NBUCKETS];
    int t = threadIdx.x;
    tmp[t] = bucket_count[t];
    __syncthreads();
    // Hillis–Steele inclusive scan
    for (int off = 1; off < NBUCKETS; off <<= 1) {
        int v = (t >= off) ? tmp[t - off] : 0;
        __syncthreads();
        tmp[t] += v;
        __syncthreads();
    }
    // exclusive start = inclusive - own count
    bucket_cursor[t] = tmp[t] - bucket_count[t];
}

// ---------------------------------------------------------------- scatter
__global__ __launch_bounds__(1024)
void k_scatter(const int* __restrict__ x) {
    int row = blockIdx.x * 1024 + threadIdx.x;
    int idx = x[row];
    int b = idx >> BUCKET_SHIFT;
    int pos = atomicAdd(&bucket_cursor[b], 1);
    sorted_key[pos] = ((unsigned long long)(unsigned)idx << 32) | (unsigned)row;
}

// ---------------------------------------------------------------- main gather
__device__ __forceinline__ float soft_thresh(float v, float sv) {
    float t = __fdividef(1.0f, 1.0f + __expf(-sv));
    float m = fmaxf(fabsf(v) - t, 0.0f);
    return copysignf(m, v);
}

__global__ __launch_bounds__(256, 8)
void k_gather(const float4* __restrict__ emb,
              const float4* __restrict__ s,
              float4* __restrict__ out) {
    // one warp per gathered row, processed in bucket-major (sorted) order
    long long gid  = (long long)blockIdx.x * blockDim.x + threadIdx.x;
    long long work = gid >> 5;
    int       comp = (int)(gid & 31);

    unsigned long long key = sorted_key[work];    // warp-uniform broadcast
    long long row = (long long)(unsigned)(key & 0xffffffffu);
    long long idx = (long long)(key >> 32);

    long long off = idx * VEC_PER_ROW + comp;
    float4 v = __ldg(&emb[off]);
    float4 t = __ldg(&s[off]);

    float4 o;
    o.x = soft_thresh(v.x, t.x);
    o.y = soft_thresh(v.y, t.y);
    o.z = soft_thresh(v.z, t.z);
    o.w = soft_thresh(v.w, t.w);

    // streaming store: don't let the 419MB write-once stream evict bucket rows
    __stcs(&out[row * VEC_PER_ROW + comp], o);
}

// ---------------------------------------------------------------- launch
extern "C" void kernel_launch(void* const* d_in, const int* in_sizes, int n_in,
                              void* d_out, int out_size) {
    const int*    x   = (const int*)d_in[0];
    const float4* emb = (const float4*)d_in[1];
    const float4* s   = (const float4*)d_in[2];
    float4*       out = (float4*)d_out;

    k_init<<<1, NBUCKETS>>>();
    k_hist<<<ROWS / 1024, 1024>>>(x);
    k_scan<<<1, NBUCKETS>>>();
    k_scatter<<<ROWS / 1024, 1024>>>(x);

    const long long total_vec = (long long)ROWS * VEC_PER_ROW;   // 26,214,400
    const int threads = 256;
    const int blocks  = (int)(total_vec / threads);               // 102,400
    k_gather<<<blocks, threads>>>(emb, s, out);
}

// round 3
// speedup vs baseline: 1.3022x; 1.3022x over previous
#include <cuda_runtime.h>
#include <cuda_bf16.h>

// PepEmbedding: out[b,h,:] = soft_threshold(emb[x[b,h],:], s[x[b,h],:])
//   soft_threshold(v,s) = sign(v)*relu(|v| - sigmoid(s))
//
// R3: bucket-major gather (L2 reuse of duplicate indices, proven ~167us in R2)
// with the counting sort rebuilt as a block-aggregated sort: shared-memory
// histograms + hierarchical scan, ZERO global atomics (R2's scatter burned
// 67us on 819K atomics over 1024 addresses).

#define ROWS        (16384 * 50)     // 819,200
#define NBUCKETS    256
#define BUCKET_SHIFT 12              // idx >> 12 -> bucket 0..244 (4096-wide)
#define NBLK        800              // 819200 / 1024
#define VEC_PER_ROW 32               // 128 floats / float4

// Scratch (device globals — allocation is forbidden)
__device__ int                cnt[NBLK * NBUCKETS];   // per-block counts -> excl offsets
__device__ int                bucket_total[NBUCKETS];
__device__ int                bucket_base[NBUCKETS];
__device__ unsigned long long sorted_key[ROWS];       // (idx << 32) | row

// ---------------------------------------------------------------- 1) histogram
__global__ __launch_bounds__(1024)
void k_hist(const int* __restrict__ x) {
    __shared__ int h[NBUCKETS];
    if (threadIdx.x < NBUCKETS) h[threadIdx.x] = 0;
    __syncthreads();

    int row = blockIdx.x * 1024 + threadIdx.x;        // grid covers ROWS exactly
    int b = x[row] >> BUCKET_SHIFT;
    atomicAdd(&h[b], 1);                              // smem atomic, ~4/bucket
    __syncthreads();

    if (threadIdx.x < NBUCKETS)
        cnt[blockIdx.x * NBUCKETS + threadIdx.x] = h[threadIdx.x];
}

// ------------------------------------------------ 2) scan counts across blocks
// one block per bucket: exclusive scan over the 800 block-counts (in place)
__global__ __launch_bounds__(1024)
void k_scanA() {
    int b = blockIdx.x;
    int g = threadIdx.x;
    __shared__ int tmp[1024];
    int v = (g < NBLK) ? cnt[g * NBUCKETS + b] : 0;
    tmp[g] = v;
    __syncthreads();
    for (int off = 1; off < 1024; off <<= 1) {
        int u = (g >= off) ? tmp[g - off] : 0;
        __syncthreads();
        tmp[g] += u;
        __syncthreads();
    }
    if (g < NBLK) cnt[g * NBUCKETS + b] = tmp[g] - v;   // exclusive
    if (g == NBLK - 1) bucket_total[b] = tmp[g];        // inclusive total
}

// ------------------------------------------------------- 3) scan bucket totals
__global__ __launch_bounds__(NBUCKETS)
void k_scanB() {
    int t = threadIdx.x;
    __shared__ int tmp[NBUCKETS];
    int v = bucket_total[t];
    tmp[t] = v;
    __syncthreads();
    for (int off = 1; off < NBUCKETS; off <<= 1) {
        int u = (t >= off) ? tmp[t - off] : 0;
        __syncthreads();
        tmp[t] += u;
        __syncthreads();
    }
    bucket_base[t] = tmp[t] - v;                        // exclusive base
}

// ---------------------------------------------------------------- 4) scatter
__global__ __launch_bounds__(1024)
void k_scatter(const int* __restrict__ x) {
    __shared__ int rank[NBUCKETS];
    if (threadIdx.x < NBUCKETS)
        rank[threadIdx.x] = bucket_base[threadIdx.x]
                          + cnt[blockIdx.x * NBUCKETS + threadIdx.x];
    __syncthreads();

    int row = blockIdx.x * 1024 + threadIdx.x;
    int idx = x[row];
    int b = idx >> BUCKET_SHIFT;
    int pos = atomicAdd(&rank[b], 1);                   // smem atomic only
    sorted_key[pos] = ((unsigned long long)(unsigned)idx << 32) | (unsigned)row;
}

// ---------------------------------------------------------------- 5) gather
__device__ __forceinline__ float soft_thresh(float v, float sv) {
    float t = __fdividef(1.0f, 1.0f + __expf(-sv));
    float m = fmaxf(fabsf(v) - t, 0.0f);
    return copysignf(m, v);
}

__global__ __launch_bounds__(256, 8)
void k_gather(const float4* __restrict__ emb,
              const float4* __restrict__ s,
              float4* __restrict__ out) {
    long long gid  = (long long)blockIdx.x * blockDim.x + threadIdx.x;
    long long work = gid >> 5;                 // one warp per gathered row
    int       comp = (int)(gid & 31);

    unsigned long long key = __ldg(&sorted_key[work]);  // warp-uniform
    long long row = (long long)(unsigned)(key & 0xffffffffu);
    long long idx = (long long)(key >> 32);

    long long off = idx * VEC_PER_ROW + comp;
    float4 v = __ldg(&emb[off]);
    float4 t = __ldg(&s[off]);

    float4 o;
    o.x = soft_thresh(v.x, t.x);
    o.y = soft_thresh(v.y, t.y);
    o.z = soft_thresh(v.z, t.z);
    o.w = soft_thresh(v.w, t.w);

    // streaming store: write-once stream must not evict bucket-resident rows
    __stcs(&out[row * VEC_PER_ROW + comp], o);
}

// ---------------------------------------------------------------- launch
extern "C" void kernel_launch(void* const* d_in, const int* in_sizes, int n_in,
                              void* d_out, int out_size) {
    const int*    x   = (const int*)d_in[0];
    const float4* emb = (const float4*)d_in[1];
    const float4* s   = (const float4*)d_in[2];
    float4*       out = (float4*)d_out;

    k_hist   <<<NBLK, 1024>>>(x);
    k_scanA  <<<NBUCKETS, 1024>>>();
    k_scanB  <<<1, NBUCKETS>>>();
    k_scatter<<<NBLK, 1024>>>(x);

    const long long total_vec = (long long)ROWS * VEC_PER_ROW;  // 26,214,400
    k_gather <<<(int)(total_vec / 256), 256>>>(emb, s, out);
}